// round 3
// baseline (speedup 1.0000x reference)
#include <cuda_runtime.h>

#define CN   8192
#define NB   4096
#define NTHR 1024
#define BPT  (NB / NTHR)   // buckets per thread = 4
#define EPT  (CN / NTHR)   // elements per thread = 8

// dynamic smem layout (bytes):
//  s_cnt   NB ints          16384
//  s_off   NB+1 ints        16388
//  s_sv2   CN floats        32768
//  s_ex2   CN floats        32768
//  s_id2   CN ints          32768
//  s_bsum  NB floats        16384
//  s_bsuf  NB+1 floats      16388
//  s_scan  NTHR ints/floats  4096
#define SMEM_BYTES (16384 + 16388 + 32768*3 + 16384 + 16388 + 4096 + 16)

__device__ __forceinline__ int bkt(float v) {
    int b = (int)(v * (float)NB);
    b = b < 0 ? 0 : b;
    return b > NB - 1 ? NB - 1 : b;
}

__global__ void __launch_bounds__(NTHR) cox_bucket_kernel(
    const float* __restrict__ theta,
    const float* __restrict__ sv,
    const float* __restrict__ cen,
    float* __restrict__ out)
{
    extern __shared__ char smem[];
    int*   s_cnt  = (int*)smem;
    int*   s_off  = (int*)(smem + 16384);
    float* s_sv2  = (float*)(smem + 16384 + 16388);
    float* s_ex2  = s_sv2 + CN;
    int*   s_id2  = (int*)(s_ex2 + CN);
    float* s_bsum = (float*)(s_id2 + CN);
    float* s_bsuf = s_bsum + NB;
    int*   s_scan = (int*)(s_bsuf + NB + 1);
    float* s_scanf = (float*)s_scan;

    const int t = threadIdx.x;

    // ---- P0/P1: zero counts, histogram ----
    #pragma unroll
    for (int b = t; b < NB; b += NTHR) s_cnt[b] = 0;
    __syncthreads();

    float svl[EPT];
    #pragma unroll
    for (int q = 0; q < EPT; q++) {
        svl[q] = __ldg(&sv[t + q * NTHR]);
        atomicAdd(&s_cnt[bkt(svl[q])], 1);
    }
    __syncthreads();

    // ---- P2: exclusive scan of counts -> offsets ----
    int c[BPT];
    int tsum = 0;
    #pragma unroll
    for (int i = 0; i < BPT; i++) { c[i] = s_cnt[t * BPT + i]; tsum += c[i]; }
    s_scan[t] = tsum;
    __syncthreads();
    #pragma unroll
    for (int d = 1; d < NTHR; d <<= 1) {
        int x = 0;
        if (t >= d) x = s_scan[t - d];
        __syncthreads();
        if (t >= d) s_scan[t] += x;
        __syncthreads();
    }
    {
        int base = s_scan[t] - tsum;   // exclusive group base
        #pragma unroll
        for (int i = 0; i < BPT; i++) { s_off[t * BPT + i] = base; base += c[i]; }
        if (t == 0) s_off[NB] = CN;
    }
    __syncthreads();

    // reset cursors
    #pragma unroll
    for (int b = t; b < NB; b += NTHR) s_cnt[b] = s_off[b];
    __syncthreads();

    // ---- P3: scatter (counting sort by bucket) ----
    #pragma unroll
    for (int q = 0; q < EPT; q++) {
        int b = bkt(svl[q]);
        int p = atomicAdd(&s_cnt[b], 1);
        s_sv2[p] = svl[q];
        s_id2[p] = t + q * NTHR;
    }
    __syncthreads();

    // ---- P4: per-bucket canonical sort by original index (bitwise-deterministic
    //          layout), compute exp and bucket sums in that fixed order ----
    #pragma unroll
    for (int i = 0; i < BPT; i++) {
        int b  = t * BPT + i;
        int lo = s_off[b], hi = s_off[b + 1];
        for (int x = lo + 1; x < hi; x++) {
            int   idv = s_id2[x];
            float svv = s_sv2[x];
            int y = x - 1;
            while (y >= lo && s_id2[y] > idv) {
                s_id2[y + 1] = s_id2[y];
                s_sv2[y + 1] = s_sv2[y];
                y--;
            }
            s_id2[y + 1] = idv;
            s_sv2[y + 1] = svv;
        }
        float bs = 0.f;
        for (int x = lo; x < hi; x++) {
            float e = __expf(__ldg(&theta[s_id2[x]]));
            s_ex2[x] = e;
            bs += e;
        }
        s_bsum[b] = bs;
    }
    __syncthreads();

    // ---- P5: suffix sums over bucket exp totals ----
    {
        float gs = 0.f;
        float g[BPT];
        #pragma unroll
        for (int i = 0; i < BPT; i++) { g[i] = s_bsum[t * BPT + i]; gs += g[i]; }
        // inclusive scan over reversed thread order -> suffix of group sums
        int u = NTHR - 1 - t;
        s_scanf[u] = gs;
        __syncthreads();
        #pragma unroll
        for (int d = 1; d < NTHR; d <<= 1) {
            float x = 0.f;
            if (u >= d) x = s_scanf[u - d];
            __syncthreads();
            if (u >= d) s_scanf[u] += x;
            __syncthreads();
        }
        float higher = s_scanf[u] - gs;   // sum of all groups above this one
        float run = higher;
        #pragma unroll
        for (int i = BPT - 1; i >= 0; i--) {
            run += g[i];
            s_bsuf[t * BPT + i] = run;    // includes own bucket
        }
        if (t == 0) s_bsuf[NB] = 0.f;
    }
    __syncthreads();

    // ---- P6: per-element contributions ----
    float acc = 0.f;
    #pragma unroll
    for (int q = 0; q < EPT; q++) {
        int   p  = t + q * NTHR;
        int   id = s_id2[p];
        float v  = s_sv2[p];
        int   b  = bkt(v);
        int   lo = s_off[b], hi = s_off[b + 1];
        float w  = 0.f;
        for (int m = lo; m < hi; m++)
            if (s_sv2[m] >= v) w += s_ex2[m];
        float risk = s_bsuf[b + 1] + w;   // strictly-higher buckets + exact same-bucket
        acc += (__ldg(&theta[id]) - __logf(risk)) * __ldg(&cen[id]);
    }
    s_scanf[t] = acc;
    __syncthreads();

    // ---- P7: fixed-order block reduce ----
    #pragma unroll
    for (int st = NTHR / 2; st > 0; st >>= 1) {
        if (t < st) s_scanf[t] += s_scanf[t + st];
        __syncthreads();
    }
    if (t == 0) out[0] = -s_scanf[0] / (float)CN;
}

extern "C" void kernel_launch(void* const* d_in, const int* in_sizes, int n_in,
                              void* d_out, int out_size) {
    const float* hazard_pred = (const float*)d_in[0];
    const float* survtime    = (const float*)d_in[1];
    const float* censor      = (const float*)d_in[2];
    float* out = (float*)d_out;

    cudaFuncSetAttribute(cox_bucket_kernel,
                         cudaFuncAttributeMaxDynamicSharedMemorySize, SMEM_BYTES);
    cox_bucket_kernel<<<1, NTHR, SMEM_BYTES>>>(hazard_pred, survtime, censor, out);
}

// round 4
// speedup vs baseline: 1.8221x; 1.8221x over previous
#include <cuda_runtime.h>

#define CN    8192
#define NB    4096
#define CAP   16
#define OVCAP 512

__device__ int   g_cnt[NB];
__device__ float g_bsum[NB];
__device__ float g_svslot[NB * CAP];
__device__ float g_eslot[NB * CAP];
__device__ float g_ovf_sv[OVCAP];
__device__ float g_ovf_e[OVCAP];
__device__ int   g_ovf_cnt;

// Monotone bucket map: b_j > b_i  =>  sv_j > sv_i ;  b_j < b_i => sv_j < sv_i.
__device__ __forceinline__ int bkt(float v) {
    float x = v * (float)NB;
    x = fminf(fmaxf(x, 0.0f), (float)(NB - 1));
    return (int)x;
}

__global__ void __launch_bounds__(512) k0_zero(float* __restrict__ out) {
    int i = blockIdx.x * blockDim.x + threadIdx.x;
    if (i < NB) { g_cnt[i] = 0; g_bsum[i] = 0.0f; }
    if (i == 0) { g_ovf_cnt = 0; out[0] = 0.0f; }
}

__global__ void __launch_bounds__(256) k1_insert(
    const float* __restrict__ theta,
    const float* __restrict__ sv)
{
    int i = blockIdx.x * blockDim.x + threadIdx.x;   // 0..8191
    float v = sv[i];
    float e = __expf(theta[i]);
    int b = bkt(v);
    int p = atomicAdd(&g_cnt[b], 1);
    if (p < CAP) {
        g_svslot[b * CAP + p] = v;
        g_eslot [b * CAP + p] = e;
        atomicAdd(&g_bsum[b], e);
    } else {
        // robustness path: handled exactly, excluded from bucket sums
        int q = atomicAdd(&g_ovf_cnt, 1);
        if (q < OVCAP) { g_ovf_sv[q] = v; g_ovf_e[q] = e; }
    }
}

__global__ void __launch_bounds__(256) k2_compute(
    const float* __restrict__ theta,
    const float* __restrict__ sv,
    const float* __restrict__ cen,
    float* __restrict__ out)
{
    __shared__ float s_suf[NB + 1];   // suffix sums over buckets
    __shared__ float s_red[256];

    const int t = threadIdx.x;

    // ---- per-block redundant suffix scan of the 4096 bucket sums ----
    float g[16];
    const float4* bs4 = reinterpret_cast<const float4*>(g_bsum);
    #pragma unroll
    for (int q = 0; q < 4; q++) {
        float4 f = bs4[t * 4 + q];
        g[q * 4 + 0] = f.x; g[q * 4 + 1] = f.y;
        g[q * 4 + 2] = f.z; g[q * 4 + 3] = f.w;
    }
    float gs = 0.0f;
    #pragma unroll
    for (int i = 0; i < 16; i++) gs += g[i];

    // reverse-order inclusive scan over the 256 chunk sums
    int u = 255 - t;
    s_red[u] = gs;
    __syncthreads();
    #pragma unroll
    for (int d = 1; d < 256; d <<= 1) {
        float x = 0.0f;
        if (u >= d) x = s_red[u - d];
        __syncthreads();
        if (u >= d) s_red[u] += x;
        __syncthreads();
    }
    float above = s_red[u] - gs;   // sum of all chunks strictly above this one

    float run = above;
    #pragma unroll
    for (int i = 15; i >= 0; i--) {
        run += g[i];
        s_suf[t * 16 + i] = run;   // suffix INCLUDING bucket t*16+i
    }
    if (t == 0) s_suf[NB] = 0.0f;
    __syncthreads();

    // ---- one row per thread ----
    const int r = blockIdx.x * 256 + t;
    const float svr = sv[r];
    const int   b   = bkt(svr);

    int cnt = g_cnt[b];
    cnt = cnt < CAP ? cnt : CAP;
    float w = 0.0f;
    const float* svs = &g_svslot[b * CAP];
    const float* evs = &g_eslot [b * CAP];
    for (int m = 0; m < cnt; m++)
        if (svs[m] >= svr) w += evs[m];

    int L = g_ovf_cnt;
    L = L < OVCAP ? L : OVCAP;
    for (int m = 0; m < L; m++)
        if (g_ovf_sv[m] >= svr) w += g_ovf_e[m];

    float risk = s_suf[b + 1] + w;   // strictly-higher buckets + exact same-bucket (+ovf)
    float acc  = (theta[r] - __logf(risk)) * cen[r];

    // ---- block reduce + atomic combine ----
    s_red[t] = acc;
    __syncthreads();
    #pragma unroll
    for (int st = 128; st > 0; st >>= 1) {
        if (t < st) s_red[t] += s_red[t + st];
        __syncthreads();
    }
    if (t == 0) atomicAdd(out, -s_red[0] / (float)CN);
}

extern "C" void kernel_launch(void* const* d_in, const int* in_sizes, int n_in,
                              void* d_out, int out_size) {
    const float* hazard_pred = (const float*)d_in[0];
    const float* survtime    = (const float*)d_in[1];
    const float* censor      = (const float*)d_in[2];
    float* out = (float*)d_out;

    k0_zero  <<<(NB + 511) / 512, 512>>>(out);
    k1_insert<<<CN / 256, 256>>>(hazard_pred, survtime);
    k2_compute<<<CN / 256, 256>>>(hazard_pred, survtime, censor, out);
}